// round 10
// baseline (speedup 1.0000x reference)
#include <cuda_runtime.h>
#include <cuda_bf16.h>
#include <math.h>
#include <stdint.h>

#define SDIM 4096
#define BDIM 4096
#define BM 128
#define BN 64
#define BK 32
#define NCH (SDIM / BK)      // 128
#define NT2 (SDIM / BN)      // 64 tiles along S
#define NSTAGE 4
#define STGB 12288           // per stage: Aq0 4K, Aq1 4K, Bq0 2K, Bq1 2K

// ---------------- scratch ----------------
__device__ float g_c[SDIM];
__device__ float g_d[SDIM];
__device__ float g_partial[(size_t)BDIM * NT2];
// int8 2-slice: row r occupies 8192 bytes; [0,4096)=q0, [4096,8192)=q1
__device__ int8_t g_xq[(size_t)BDIM * 8192];
__device__ int8_t g_wq[(size_t)SDIM * 8192];

// ---------------- helpers ----------------
__device__ __forceinline__ float gelu_exact(float x) {
    return 0.5f * x * (1.0f + erff(x * 0.70710678118654752f));
}

__device__ __forceinline__ uint32_t smem_u32(const void* p) {
    uint32_t a;
    asm("{ .reg .u64 t; cvta.to.shared.u64 t, %1; cvt.u32.u64 %0, t; }" : "=r"(a) : "l"(p));
    return a;
}

// swizzle for 32B rows: XOR byte bit4 with row bit2 (off bit 7)
__device__ __forceinline__ uint32_t swz(uint32_t off) {
    return off ^ ((off >> 3) & 0x10);
}

#define CP_ASYNC_16(dst, src) \
    asm volatile("cp.async.cg.shared.global [%0], [%1], 16;" :: "r"(dst), "l"(src))
#define CP_COMMIT() asm volatile("cp.async.commit_group;" ::: "memory")
#define CP_WAIT(n)  asm volatile("cp.async.wait_group %0;" :: "n"(n) : "memory")

#define LDSM_X4(r0, r1, r2, r3, addr) \
    asm volatile("ldmatrix.sync.aligned.m8n8.x4.shared.b16 {%0,%1,%2,%3}, [%4];" \
        : "=r"(r0), "=r"(r1), "=r"(r2), "=r"(r3) : "r"(addr))

__device__ __forceinline__ void imma16832(int* c, uint32_t a0, uint32_t a1, uint32_t a2, uint32_t a3,
                                          uint32_t b0, uint32_t b1) {
    asm volatile("mma.sync.aligned.m16n8k32.row.col.s32.s8.s8.s32 "
        "{%0,%1,%2,%3}, {%4,%5,%6,%7}, {%8,%9}, {%0,%1,%2,%3};"
        : "+r"(c[0]), "+r"(c[1]), "+r"(c[2]), "+r"(c[3])
        : "r"(a0), "r"(a1), "r"(a2), "r"(a3), "r"(b0), "r"(b1));
}

// ---------------- quantization: fp32 -> int8 2-slice ----------------
// X = v*s1 ; q0 = rint(X/128) = rint(v*s0) ; q1 = rint(X) - 128*q0
__global__ void quant_kernel(const float* __restrict__ src, int8_t* __restrict__ dst,
                             float s0, float s1) {
    size_t i = ((size_t)blockIdx.x * blockDim.x + threadIdx.x) * 4;
    size_t row = i >> 12, col = i & 4095;
    float4 v = *(const float4*)(src + i);
    int q0x = __float2int_rn(v.x * s0), q0y = __float2int_rn(v.y * s0);
    int q0z = __float2int_rn(v.z * s0), q0w = __float2int_rn(v.w * s0);
    int q1x = __float2int_rn(v.x * s1) - (q0x << 7);
    int q1y = __float2int_rn(v.y * s1) - (q0y << 7);
    int q1z = __float2int_rn(v.z * s1) - (q0z << 7);
    int q1w = __float2int_rn(v.w * s1) - (q0w << 7);
    uint32_t p0 = (q0x & 0xff) | ((q0y & 0xff) << 8) | ((q0z & 0xff) << 16) | ((uint32_t)(q0w & 0xff) << 24);
    uint32_t p1 = (q1x & 0xff) | ((q1y & 0xff) << 8) | ((q1z & 0xff) << 16) | ((uint32_t)(q1w & 0xff) << 24);
    size_t base = row * 8192 + col;
    *(uint32_t*)(dst + base)        = p0;
    *(uint32_t*)(dst + base + 4096) = p1;
}

// ---------------- prologue kernels ----------------
__device__ __forceinline__ float block_reduce_sum(float v, float* sbuf) {
    int lane = threadIdx.x & 31, warp = threadIdx.x >> 5;
    #pragma unroll
    for (int o = 16; o > 0; o >>= 1) v += __shfl_down_sync(0xffffffffu, v, o);
    if (lane == 0) sbuf[warp] = v;
    __syncthreads();
    if (warp == 0) {
        v = (lane < ((int)blockDim.x >> 5)) ? sbuf[lane] : 0.0f;
        #pragma unroll
        for (int o = 16; o > 0; o >>= 1) v += __shfl_down_sync(0xffffffffu, v, o);
    }
    return v;
}

__global__ void compute_c_kernel(const float* __restrict__ sgu_proj_w,
                                 const float* __restrict__ sgu_proj_b,
                                 const float* __restrict__ ln1_b,
                                 const float* __restrict__ cp1_w,
                                 const float* __restrict__ cp1_b,
                                 const float* __restrict__ sgu_ln_b,
                                 const float* __restrict__ cp2_w,
                                 const float* __restrict__ cp2_b) {
    __shared__ float sbuf[8];
    int s = blockIdx.x;
    float total = 0.0f;
    #pragma unroll
    for (int i = 0; i < 2; ++i) {
        const float* row = sgu_proj_w + (size_t)i * SDIM * SDIM + (size_t)s * SDIM;
        float acc = 0.0f;
        for (int t = threadIdx.x * 4; t < SDIM; t += blockDim.x * 4) {
            float4 v = *(const float4*)(row + t);
            acc += (v.x + v.y) + (v.z + v.w);
        }
        float rowsum = block_reduce_sum(acc, sbuf);
        if (threadIdx.x == 0) {
            float tln = ln1_b[i];  // LN over size-1 axis == bias
            float Gu  = gelu_exact(tln * cp1_w[i * 2 + 0] + cp1_b[i * 2 + 0]);
            float vp  = sgu_ln_b[i] * rowsum + sgu_proj_b[(size_t)i * SDIM + s];
            total += (Gu * vp) * cp2_w[i] + cp2_b[i];
        }
        __syncthreads();
    }
    if (threadIdx.x == 0) g_c[s] = total;
}

__global__ void compute_d_kernel(const float* __restrict__ pooler_w,
                                 const float* __restrict__ pooler_b) {
    __shared__ float sbuf[8];
    int sp = blockIdx.x;
    const float* row = pooler_w + (size_t)sp * SDIM;
    float acc = 0.0f;
    for (int t = threadIdx.x * 4; t < SDIM; t += blockDim.x * 4) {
        float4 v = *(const float4*)(row + t);
        acc += v.x * g_c[t] + v.y * g_c[t + 1] + v.z * g_c[t + 2] + v.w * g_c[t + 3];
    }
    float v = block_reduce_sum(acc, sbuf);
    if (threadIdx.x == 0) g_d[sp] = v + pooler_b[sp];
}

// ---------------- int8 2-slice GEMM, cp.async 4-stage, occ 2 ----------------
// stage layout: Aq0 @0 (4K), Aq1 @4096, Bq0 @8192 (2K), Bq1 @10240
__global__ void __launch_bounds__(256, 2)
gemm_imma_kernel(const float* __restrict__ clsw) {
    extern __shared__ __align__(1024) char smem[];
    const uint32_t sb = smem_u32(smem);

    const int tid  = threadIdx.x;
    const int lane = tid & 31;
    const int wid  = tid >> 5;
    const int g    = lane >> 2;
    const int t4   = lane & 3;
    const int wm   = (wid & 3) * 32;     // warp M offset
    const int wn   = (wid >> 2) * 32;    // warp N offset (2 warps in N)
    const int bB   = blockIdx.y * BM;
    const int bS   = blockIdx.x * BN;

    // producer mapping: 3 cp.async per thread
    const int prow = tid >> 1;           // A row 0..127
    const int pcb  = (tid & 1) * 16;     // 16B half of 32B chunk
    const char* XB = (const char*)g_xq + (size_t)(bB + prow) * 8192 + pcb;   // q0 (q1 at +4096)
    const uint32_t dA = swz((uint32_t)(prow * 32 + pcb));
    const int brow = (tid >> 1) & 63;    // B row 0..63
    const int bsl  = tid >> 7;           // 0:q0, 1:q1
    const char* WB = (const char*)g_wq + (size_t)(bS + brow) * 8192 + bsl * 4096 + pcb;
    const uint32_t dB = 8192 + (uint32_t)bsl * 2048 + swz((uint32_t)(brow * 32 + pcb));

    // ldmatrix offsets (pre-swizzle folding; rows are 32B)
    uint32_t offA[2], offB[2];
    {
        int r = lane & 15, kc = lane >> 4;
        #pragma unroll
        for (int mt = 0; mt < 2; ++mt)
            offA[mt] = swz((uint32_t)((wm + mt * 16 + r) * 32 + kc * 16));
        int rb = (lane & 7) + ((lane >> 4) << 3), kcb = (lane >> 3) & 1;
        #pragma unroll
        for (int np = 0; np < 2; ++np)
            offB[np] = swz((uint32_t)((wn + np * 16 + rb) * 32 + kcb * 16));
    }

    int hi[2][4][4], mid[2][4][4];
    #pragma unroll
    for (int mt = 0; mt < 2; ++mt)
        #pragma unroll
        for (int nt = 0; nt < 4; ++nt)
            #pragma unroll
            for (int c = 0; c < 4; ++c) { hi[mt][nt][c] = 0; mid[mt][nt][c] = 0; }

    auto issue = [&](int stage, int ch) {
        const uint32_t stb = sb + stage * STGB;
        const int ko = ch * BK;              // byte offset within q0 (q1 mirrors at +4096)
        CP_ASYNC_16(stb + dA,        XB + ko);
        CP_ASYNC_16(stb + 4096 + dA, XB + 4096 + ko);
        CP_ASYNC_16(stb + dB,        WB + ko);
    };

    #pragma unroll
    for (int s = 0; s < NSTAGE - 1; ++s) { issue(s, s); CP_COMMIT(); }

    int rd = 0, wr = NSTAGE - 1;
    #pragma unroll 1
    for (int ch = 0; ch < NCH; ++ch) {
        CP_WAIT(NSTAGE - 2);
        __syncthreads();

        if (ch + NSTAGE - 1 < NCH) issue(wr, ch + NSTAGE - 1);
        CP_COMMIT();
        if (++wr == NSTAGE) wr = 0;

        const uint32_t stb = sb + rd * STGB;
        if (++rd == NSTAGE) rd = 0;

        uint32_t a0[2][4], a1[2][4];
        #pragma unroll
        for (int mt = 0; mt < 2; ++mt) {
            LDSM_X4(a0[mt][0], a0[mt][1], a0[mt][2], a0[mt][3], stb + offA[mt]);
            LDSM_X4(a1[mt][0], a1[mt][1], a1[mt][2], a1[mt][3], stb + 4096 + offA[mt]);
        }
        #pragma unroll
        for (int np = 0; np < 2; ++np) {
            uint32_t b0[4], b1[4];
            LDSM_X4(b0[0], b0[1], b0[2], b0[3], stb + 8192  + offB[np]);
            LDSM_X4(b1[0], b1[1], b1[2], b1[3], stb + 10240 + offB[np]);
            #pragma unroll
            for (int mt = 0; mt < 2; ++mt) {
                #pragma unroll
                for (int j = 0; j < 2; ++j) {
                    int* cH = hi[mt][np * 2 + j];
                    int* cM = mid[mt][np * 2 + j];
                    imma16832(cH, a0[mt][0], a0[mt][1], a0[mt][2], a0[mt][3], b0[2*j], b0[2*j+1]);
                    imma16832(cM, a0[mt][0], a0[mt][1], a0[mt][2], a0[mt][3], b1[2*j], b1[2*j+1]);
                    imma16832(cM, a1[mt][0], a1[mt][1], a1[mt][2], a1[mt][3], b0[2*j], b0[2*j+1]);
                }
            }
        }
    }

    // ---------------- fused epilogue ----------------
    CP_WAIT(0);
    float rs[4] = {0.0f, 0.0f, 0.0f, 0.0f};   // (mt, half)
    #pragma unroll
    for (int nt = 0; nt < 4; ++nt) {
        int col0 = bS + wn + nt * 8 + 2 * t4;
        float dd0 = g_d[col0],     w0 = clsw[col0];
        float dd1 = g_d[col0 + 1], w1 = clsw[col0 + 1];
        #pragma unroll
        for (int mt = 0; mt < 2; ++mt) {
            float y00 = (float)hi[mt][nt][0] * 0x1p-16f + (float)mid[mt][nt][0] * 0x1p-23f;
            float y01 = (float)hi[mt][nt][1] * 0x1p-16f + (float)mid[mt][nt][1] * 0x1p-23f;
            float y10 = (float)hi[mt][nt][2] * 0x1p-16f + (float)mid[mt][nt][2] * 0x1p-23f;
            float y11 = (float)hi[mt][nt][3] * 0x1p-16f + (float)mid[mt][nt][3] * 0x1p-23f;
            rs[mt * 2 + 0] += gelu_exact(y00 + dd0) * w0 + gelu_exact(y01 + dd1) * w1;
            rs[mt * 2 + 1] += gelu_exact(y10 + dd0) * w0 + gelu_exact(y11 + dd1) * w1;
        }
    }
    #pragma unroll
    for (int o = 1; o <= 2; o <<= 1) {
        #pragma unroll
        for (int i = 0; i < 4; ++i) rs[i] += __shfl_xor_sync(0xffffffffu, rs[i], o);
    }

    float* redbuf = (float*)smem;   // [2][128]
    __syncthreads();
    if (t4 == 0) {
        #pragma unroll
        for (int mt = 0; mt < 2; ++mt)
            #pragma unroll
            for (int h = 0; h < 2; ++h) {
                int row = wm + mt * 16 + h * 8 + g;
                redbuf[(wid >> 2) * 128 + row] = rs[mt * 2 + h];
            }
    }
    __syncthreads();
    if (tid < 128) {
        float p = redbuf[tid] + redbuf[128 + tid];
        g_partial[(size_t)(bB + tid) * NT2 + blockIdx.x] = p;
    }
}

__global__ void final_kernel(const float* __restrict__ cls_b, float* __restrict__ out) {
    int b = blockIdx.x * blockDim.x + threadIdx.x;
    if (b < BDIM) {
        float sum = 0.0f;
        #pragma unroll
        for (int j = 0; j < NT2; ++j) sum += g_partial[(size_t)b * NT2 + j];
        out[b] = sum + cls_b[0];
    }
}

// ---------------- launch ----------------
extern "C" void kernel_launch(void* const* d_in, const int* in_sizes, int n_in,
                              void* d_out, int out_size) {
    const float* x          = (const float*)d_in[0];
    const float* ln1_b      = (const float*)d_in[2];
    const float* cp1_w      = (const float*)d_in[3];
    const float* cp1_b      = (const float*)d_in[4];
    const float* sgu_ln_b   = (const float*)d_in[6];
    const float* sgu_proj_w = (const float*)d_in[7];
    const float* sgu_proj_b = (const float*)d_in[8];
    const float* cp2_w      = (const float*)d_in[9];
    const float* cp2_b      = (const float*)d_in[10];
    const float* pooler_w   = (const float*)d_in[11];
    const float* pooler_b   = (const float*)d_in[12];
    const float* cls_w      = (const float*)d_in[13];
    const float* cls_b      = (const float*)d_in[14];

    cudaFuncSetAttribute(gemm_imma_kernel, cudaFuncAttributeMaxDynamicSharedMemorySize,
                         NSTAGE * STGB);

    int8_t *xq, *wq;
    cudaGetSymbolAddress((void**)&xq, g_xq);
    cudaGetSymbolAddress((void**)&wq, g_wq);

    // x: X = x*2^11 -> s0 = 2^11/128 = 16, s1 = 2048
    quant_kernel<<<(size_t)BDIM * SDIM / 1024, 256>>>(x, xq, 16.0f, 2048.0f);
    // w: W = w*2^19 -> s0 = 2^19/128 = 4096, s1 = 524288
    quant_kernel<<<(size_t)SDIM * SDIM / 1024, 256>>>(pooler_w, wq, 4096.0f, 524288.0f);

    compute_c_kernel<<<SDIM, 256>>>(sgu_proj_w, sgu_proj_b, ln1_b, cp1_w, cp1_b,
                                    sgu_ln_b, cp2_w, cp2_b);
    compute_d_kernel<<<SDIM, 256>>>(pooler_w, pooler_b);

    dim3 grid(SDIM / BN, BDIM / BM);   // (64, 32)
    gemm_imma_kernel<<<grid, 256, NSTAGE * STGB>>>(cls_w);

    final_kernel<<<(BDIM + 255) / 256, 256>>>(cls_b, (float*)d_out);
}

// round 12
// speedup vs baseline: 1.8367x; 1.8367x over previous
#include <cuda_runtime.h>
#include <cuda_bf16.h>
#include <math.h>
#include <stdint.h>

#define SDIM 4096
#define BDIM 4096
#define BM 256
#define BN 128
#define BK 32
#define NCH (SDIM / BK)      // 128
#define NTILE (SDIM / BN)    // 32

// ---------------- scratch ----------------
__device__ float g_c[SDIM];
__device__ float g_d[SDIM];
__device__ float g_partial[(size_t)BDIM * NTILE];
// fragment-major: [slice][R16*256 + K16] -> 32 lanes x 16B
__device__ uint4 g_xf[2][(size_t)256 * 256 * 32];
__device__ uint4 g_wf[2][(size_t)256 * 256 * 32];

// ---------------- helpers ----------------
__device__ __forceinline__ float gelu_exact(float x) {
    return 0.5f * x * (1.0f + erff(x * 0.70710678118654752f));
}

__device__ __forceinline__ void mma16816(float* c, uint32_t a0, uint32_t a1, uint32_t a2, uint32_t a3,
                                         uint32_t b0, uint32_t b1) {
    asm volatile("mma.sync.aligned.m16n8k16.row.col.f32.bf16.bf16.f32 "
        "{%0,%1,%2,%3}, {%4,%5,%6,%7}, {%8,%9}, {%0,%1,%2,%3};"
        : "+f"(c[0]), "+f"(c[1]), "+f"(c[2]), "+f"(c[3])
        : "r"(a0), "r"(a1), "r"(a2), "r"(a3), "r"(b0), "r"(b1));
}

__device__ __forceinline__ uint32_t pack_bf16(__nv_bfloat16 a, __nv_bfloat16 b) {
    return (uint32_t)__bfloat16_as_ushort(a) | ((uint32_t)__bfloat16_as_ushort(b) << 16);
}

__device__ __forceinline__ uint32_t hi_pair(float2 v, float2* lo) {
    __nv_bfloat16 h0 = __float2bfloat16_rn(v.x), h1 = __float2bfloat16_rn(v.y);
    lo->x = v.x - __bfloat162float(h0);
    lo->y = v.y - __bfloat162float(h1);
    return pack_bf16(h0, h1);
}
__device__ __forceinline__ uint32_t lo_pair(float2 l) {
    return pack_bf16(__float2bfloat16_rn(l.x), __float2bfloat16_rn(l.y));
}

// ---------------- conversion: fp32 -> fragment-major bf16 hi/lo ----------------
// one thread per (block, lane); block = R16*256 + K16
__global__ void convert_frag_kernel(const float* __restrict__ src,
                                    uint4* __restrict__ dh, uint4* __restrict__ dl) {
    size_t t = (size_t)blockIdx.x * blockDim.x + threadIdx.x;  // 256*256*32 total
    int lane = (int)(t & 31);
    size_t blk = t >> 5;
    int R16 = (int)(blk >> 8), K16 = (int)(blk & 255);
    int r = R16 * 16 + (lane >> 2);
    int k = K16 * 16 + 2 * (lane & 3);
    float2 v00 = *(const float2*)(src + (size_t)r * SDIM + k);
    float2 v10 = *(const float2*)(src + (size_t)(r + 8) * SDIM + k);
    float2 v01 = *(const float2*)(src + (size_t)r * SDIM + k + 8);
    float2 v11 = *(const float2*)(src + (size_t)(r + 8) * SDIM + k + 8);
    float2 l00, l10, l01, l11;
    uint4 h, l;
    h.x = hi_pair(v00, &l00); h.y = hi_pair(v10, &l10);
    h.z = hi_pair(v01, &l01); h.w = hi_pair(v11, &l11);
    l.x = lo_pair(l00); l.y = lo_pair(l10); l.z = lo_pair(l01); l.w = lo_pair(l11);
    dh[t] = h;
    dl[t] = l;
}

// ---------------- prologue kernels ----------------
__device__ __forceinline__ float block_reduce_sum(float v, float* sbuf) {
    int lane = threadIdx.x & 31, warp = threadIdx.x >> 5;
    #pragma unroll
    for (int o = 16; o > 0; o >>= 1) v += __shfl_down_sync(0xffffffffu, v, o);
    if (lane == 0) sbuf[warp] = v;
    __syncthreads();
    if (warp == 0) {
        v = (lane < ((int)blockDim.x >> 5)) ? sbuf[lane] : 0.0f;
        #pragma unroll
        for (int o = 16; o > 0; o >>= 1) v += __shfl_down_sync(0xffffffffu, v, o);
    }
    return v;
}

__global__ void compute_c_kernel(const float* __restrict__ sgu_proj_w,
                                 const float* __restrict__ sgu_proj_b,
                                 const float* __restrict__ ln1_b,
                                 const float* __restrict__ cp1_w,
                                 const float* __restrict__ cp1_b,
                                 const float* __restrict__ sgu_ln_b,
                                 const float* __restrict__ cp2_w,
                                 const float* __restrict__ cp2_b) {
    __shared__ float sbuf[8];
    int s = blockIdx.x;
    float total = 0.0f;
    #pragma unroll
    for (int i = 0; i < 2; ++i) {
        const float* row = sgu_proj_w + (size_t)i * SDIM * SDIM + (size_t)s * SDIM;
        float acc = 0.0f;
        for (int t = threadIdx.x * 4; t < SDIM; t += blockDim.x * 4) {
            float4 v = *(const float4*)(row + t);
            acc += (v.x + v.y) + (v.z + v.w);
        }
        float rowsum = block_reduce_sum(acc, sbuf);
        if (threadIdx.x == 0) {
            float tln = ln1_b[i];  // LN over size-1 axis == bias
            float Gu  = gelu_exact(tln * cp1_w[i * 2 + 0] + cp1_b[i * 2 + 0]);
            float vp  = sgu_ln_b[i] * rowsum + sgu_proj_b[(size_t)i * SDIM + s];
            total += (Gu * vp) * cp2_w[i] + cp2_b[i];
        }
        __syncthreads();
    }
    if (threadIdx.x == 0) g_c[s] = total;
}

__global__ void compute_d_kernel(const float* __restrict__ pooler_w,
                                 const float* __restrict__ pooler_b) {
    __shared__ float sbuf[8];
    int sp = blockIdx.x;
    const float* row = pooler_w + (size_t)sp * SDIM;
    float acc = 0.0f;
    for (int t = threadIdx.x * 4; t < SDIM; t += blockDim.x * 4) {
        float4 v = *(const float4*)(row + t);
        acc += v.x * g_c[t] + v.y * g_c[t + 1] + v.z * g_c[t + 2] + v.w * g_c[t + 3];
    }
    float v = block_reduce_sum(acc, sbuf);
    if (threadIdx.x == 0) g_d[sp] = v + pooler_b[sp];
}

// ---------------- bf16 3-split GEMM, direct-LDG fragments, no smem ----------------
// 8 warps: warp tile 64x64; CTA tile 256x128. No smem in mainloop.
__global__ void __launch_bounds__(256, 1)
gemm_hmma_kernel(const float* __restrict__ clsw) {
    __shared__ float redbuf[2][256];

    const int tid  = threadIdx.x;
    const int lane = tid & 31;
    const int wid  = tid >> 5;
    const int g    = lane >> 2;
    const int t4   = lane & 3;
    const int wm   = (wid & 3) * 64;     // 4 warps in M
    const int wn   = (wid >> 2) * 64;    // 2 warps in N
    const int bB   = blockIdx.y * BM;
    const int bS   = blockIdx.x * BN;

    // fragment-block bases: R16 = (bB+wm)/16 + mt ; N16 = (bS+wn)/16 + nt ; K16 = ch*2 + kb
    const size_t aBase = ((size_t)((bB + wm) >> 4) * 256) * 32 + lane;
    const size_t bBase = ((size_t)((bS + wn) >> 4) * 256) * 32 + lane;
    const uint4* pAh = g_xf[0] + aBase;
    const uint4* pAl = g_xf[1] + aBase;
    const uint4* pBh = g_wf[0] + bBase;
    const uint4* pBl = g_wf[1] + bBase;

    float acc[4][8][4];
    #pragma unroll
    for (int mt = 0; mt < 4; ++mt)
        #pragma unroll
        for (int nq = 0; nq < 8; ++nq)
            #pragma unroll
            for (int c = 0; c < 4; ++c) acc[mt][nq][c] = 0.0f;

    #pragma unroll 1
    for (int ch = 0; ch < NCH; ++ch) {
        // load all A fragments for this chunk: [slice][mt][kb]
        uint4 Ah[4][2], Al[4][2];
        #pragma unroll
        for (int mt = 0; mt < 4; ++mt)
            #pragma unroll
            for (int kb = 0; kb < 2; ++kb) {
                size_t o = (size_t)(mt * 256 + kb) * 32;   // mt stride: 256 K16-blocks
                Ah[mt][kb] = pAh[o];
                Al[mt][kb] = pAl[o];
            }
        #pragma unroll
        for (int kb = 0; kb < 2; ++kb) {
            #pragma unroll
            for (int nt = 0; nt < 4; ++nt) {
                size_t o = (size_t)(nt * 256 + kb) * 32;
                uint4 Bh = pBh[o];
                uint4 Bl = pBl[o];
                #pragma unroll
                for (int mt = 0; mt < 4; ++mt) {
                    // j=0: B regs (x,z); j=1: (y,w)
                    float* c0 = acc[mt][nt * 2 + 0];
                    float* c1 = acc[mt][nt * 2 + 1];
                    mma16816(c0, Ah[mt][kb].x, Ah[mt][kb].y, Ah[mt][kb].z, Ah[mt][kb].w, Bh.x, Bh.z);
                    mma16816(c0, Ah[mt][kb].x, Ah[mt][kb].y, Ah[mt][kb].z, Ah[mt][kb].w, Bl.x, Bl.z);
                    mma16816(c0, Al[mt][kb].x, Al[mt][kb].y, Al[mt][kb].z, Al[mt][kb].w, Bh.x, Bh.z);
                    mma16816(c1, Ah[mt][kb].x, Ah[mt][kb].y, Ah[mt][kb].z, Ah[mt][kb].w, Bh.y, Bh.w);
                    mma16816(c1, Ah[mt][kb].x, Ah[mt][kb].y, Ah[mt][kb].z, Ah[mt][kb].w, Bl.y, Bl.w);
                    mma16816(c1, Al[mt][kb].x, Al[mt][kb].y, Al[mt][kb].z, Al[mt][kb].w, Bh.y, Bh.w);
                }
            }
        }
        pAh += 64; pAl += 64; pBh += 64; pBl += 64;   // 2 K16-blocks * 32
    }

    // ---------------- fused epilogue ----------------
    float rs[8];
    #pragma unroll
    for (int i = 0; i < 8; ++i) rs[i] = 0.0f;
    #pragma unroll
    for (int nq = 0; nq < 8; ++nq) {
        int col0 = bS + wn + nq * 8 + 2 * t4;
        float dd0 = g_d[col0],     w0 = clsw[col0];
        float dd1 = g_d[col0 + 1], w1 = clsw[col0 + 1];
        #pragma unroll
        for (int mt = 0; mt < 4; ++mt) {
            rs[mt * 2 + 0] += gelu_exact(acc[mt][nq][0] + dd0) * w0
                            + gelu_exact(acc[mt][nq][1] + dd1) * w1;
            rs[mt * 2 + 1] += gelu_exact(acc[mt][nq][2] + dd0) * w0
                            + gelu_exact(acc[mt][nq][3] + dd1) * w1;
        }
    }
    #pragma unroll
    for (int o = 1; o <= 2; o <<= 1) {
        #pragma unroll
        for (int i = 0; i < 8; ++i) rs[i] += __shfl_xor_sync(0xffffffffu, rs[i], o);
    }
    if (t4 == 0) {
        #pragma unroll
        for (int mt = 0; mt < 4; ++mt)
            #pragma unroll
            for (int h = 0; h < 2; ++h)
                redbuf[wid >> 2][wm + mt * 16 + h * 8 + g] = rs[mt * 2 + h];
    }
    __syncthreads();
    if (tid < 256) {
        float p = redbuf[0][tid] + redbuf[1][tid];
        g_partial[(size_t)(bB + tid) * NTILE + blockIdx.x] = p;
    }
}

__global__ void final_kernel(const float* __restrict__ cls_b, float* __restrict__ out) {
    int b = blockIdx.x * blockDim.x + threadIdx.x;
    if (b < BDIM) {
        float sum = 0.0f;
        #pragma unroll
        for (int j = 0; j < NTILE; ++j) sum += g_partial[(size_t)b * NTILE + j];
        out[b] = sum + cls_b[0];
    }
}

// ---------------- launch ----------------
extern "C" void kernel_launch(void* const* d_in, const int* in_sizes, int n_in,
                              void* d_out, int out_size) {
    const float* x          = (const float*)d_in[0];
    const float* ln1_b      = (const float*)d_in[2];
    const float* cp1_w      = (const float*)d_in[3];
    const float* cp1_b      = (const float*)d_in[4];
    const float* sgu_ln_b   = (const float*)d_in[6];
    const float* sgu_proj_w = (const float*)d_in[7];
    const float* sgu_proj_b = (const float*)d_in[8];
    const float* cp2_w      = (const float*)d_in[9];
    const float* cp2_b      = (const float*)d_in[10];
    const float* pooler_w   = (const float*)d_in[11];
    const float* pooler_b   = (const float*)d_in[12];
    const float* cls_w      = (const float*)d_in[13];
    const float* cls_b      = (const float*)d_in[14];

    uint4 *xfh, *xfl, *wfh, *wfl;
    cudaGetSymbolAddress((void**)&xfh, g_xf);
    cudaGetSymbolAddress((void**)&wfh, g_wf);
    xfl = xfh + (size_t)256 * 256 * 32;
    wfl = wfh + (size_t)256 * 256 * 32;

    const size_t nfrag = (size_t)256 * 256 * 32;       // 2.1M threads
    convert_frag_kernel<<<nfrag / 256, 256>>>(x, xfh, xfl);
    convert_frag_kernel<<<nfrag / 256, 256>>>(pooler_w, wfh, wfl);

    compute_c_kernel<<<SDIM, 256>>>(sgu_proj_w, sgu_proj_b, ln1_b, cp1_w, cp1_b,
                                    sgu_ln_b, cp2_w, cp2_b);
    compute_d_kernel<<<SDIM, 256>>>(pooler_w, pooler_b);

    dim3 grid(SDIM / BN, BDIM / BM);   // (32, 16)
    gemm_hmma_kernel<<<grid, 256>>>(cls_w);

    final_kernel<<<(BDIM + 255) / 256, 256>>>(cls_b, (float*)d_out);
}

// round 15
// speedup vs baseline: 3.6640x; 1.9949x over previous
#include <cuda_runtime.h>
#include <cuda_fp16.h>
#include <math.h>
#include <stdint.h>

#define SDIM 4096
#define BDIM 4096
#define BM 128
#define BN 128
#define BK 32
#define NCH (SDIM / BK)      // 128
#define NTILE (SDIM / BN)    // 32
#define NSTAGE 4
#define STGB 24576           // per stage: Ah 8K, Al 8K, Bq 8K

// ---------------- scratch ----------------
__device__ float g_c[SDIM];
__device__ float g_d[SDIM];
__device__ float g_partial[(size_t)BDIM * NTILE];
// x: interleaved hi/lo fp16; row r occupies 8192 halfs: [0,4096)=hi, [4096,8192)=lo
__device__ __half g_xs[(size_t)BDIM * 8192];
// w: plain fp16
__device__ __half g_wq[(size_t)SDIM * 4096];

// ---------------- helpers ----------------
__device__ __forceinline__ float gelu_exact(float x) {
    return 0.5f * x * (1.0f + erff(x * 0.70710678118654752f));
}

__device__ __forceinline__ uint32_t smem_u32(const void* p) {
    uint32_t a;
    asm("{ .reg .u64 t; cvta.to.shared.u64 t, %1; cvt.u32.u64 %0, t; }" : "=r"(a) : "l"(p));
    return a;
}

// swizzle for 64B rows: XOR byte bits [5:4] with row bits (off bits [8:7])
__device__ __forceinline__ uint32_t swz(uint32_t off) {
    return off ^ ((off >> 3) & 0x30);
}

#define CP_ASYNC_16(dst, src) \
    asm volatile("cp.async.cg.shared.global [%0], [%1], 16;" :: "r"(dst), "l"(src))
#define CP_COMMIT() asm volatile("cp.async.commit_group;" ::: "memory")
#define CP_WAIT(n)  asm volatile("cp.async.wait_group %0;" :: "n"(n) : "memory")

#define LDSM_X4(r0, r1, r2, r3, addr) \
    asm volatile("ldmatrix.sync.aligned.m8n8.x4.shared.b16 {%0,%1,%2,%3}, [%4];" \
        : "=r"(r0), "=r"(r1), "=r"(r2), "=r"(r3) : "r"(addr))

__device__ __forceinline__ void mma16816(float* c, uint32_t a0, uint32_t a1, uint32_t a2, uint32_t a3,
                                         uint32_t b0, uint32_t b1) {
    asm volatile("mma.sync.aligned.m16n8k16.row.col.f32.f16.f16.f32 "
        "{%0,%1,%2,%3}, {%4,%5,%6,%7}, {%8,%9}, {%0,%1,%2,%3};"
        : "+f"(c[0]), "+f"(c[1]), "+f"(c[2]), "+f"(c[3])
        : "r"(a0), "r"(a1), "r"(a2), "r"(a3), "r"(b0), "r"(b1));
}

__device__ __forceinline__ uint32_t pack_h2(__half a, __half b) {
    return (uint32_t)__half_as_ushort(a) | ((uint32_t)__half_as_ushort(b) << 16);
}

// ---------------- conversion kernels ----------------
// x -> fp16 hi + fp16 residual, interleaved per row
__global__ void convert_x_kernel(const float* __restrict__ src, __half* __restrict__ dst) {
    size_t i = ((size_t)blockIdx.x * blockDim.x + threadIdx.x) * 4;
    size_t row = i >> 12, col = i & 4095;
    float4 v = *(const float4*)(src + i);
    __half h0 = __float2half_rn(v.x), h1 = __float2half_rn(v.y);
    __half h2 = __float2half_rn(v.z), h3 = __float2half_rn(v.w);
    __half l0 = __float2half_rn(v.x - __half2float(h0));
    __half l1 = __float2half_rn(v.y - __half2float(h1));
    __half l2 = __float2half_rn(v.z - __half2float(h2));
    __half l3 = __float2half_rn(v.w - __half2float(h3));
    size_t base = row * 8192 + col;
    *(uint2*)(dst + base)        = make_uint2(pack_h2(h0, h1), pack_h2(h2, h3));
    *(uint2*)(dst + base + 4096) = make_uint2(pack_h2(l0, l1), pack_h2(l2, l3));
}

// w -> plain fp16
__global__ void convert_w_kernel(const float* __restrict__ src, __half* __restrict__ dst) {
    size_t i = ((size_t)blockIdx.x * blockDim.x + threadIdx.x) * 4;
    float4 v = *(const float4*)(src + i);
    *(uint2*)(dst + i) = make_uint2(pack_h2(__float2half_rn(v.x), __float2half_rn(v.y)),
                                    pack_h2(__float2half_rn(v.z), __float2half_rn(v.w)));
}

// ---------------- prologue kernels ----------------
__device__ __forceinline__ float block_reduce_sum(float v, float* sbuf) {
    int lane = threadIdx.x & 31, warp = threadIdx.x >> 5;
    #pragma unroll
    for (int o = 16; o > 0; o >>= 1) v += __shfl_down_sync(0xffffffffu, v, o);
    if (lane == 0) sbuf[warp] = v;
    __syncthreads();
    if (warp == 0) {
        v = (lane < ((int)blockDim.x >> 5)) ? sbuf[lane] : 0.0f;
        #pragma unroll
        for (int o = 16; o > 0; o >>= 1) v += __shfl_down_sync(0xffffffffu, v, o);
    }
    return v;
}

__global__ void compute_c_kernel(const float* __restrict__ sgu_proj_w,
                                 const float* __restrict__ sgu_proj_b,
                                 const float* __restrict__ ln1_b,
                                 const float* __restrict__ cp1_w,
                                 const float* __restrict__ cp1_b,
                                 const float* __restrict__ sgu_ln_b,
                                 const float* __restrict__ cp2_w,
                                 const float* __restrict__ cp2_b) {
    __shared__ float sbuf[8];
    int s = blockIdx.x;
    float total = 0.0f;
    #pragma unroll
    for (int i = 0; i < 2; ++i) {
        const float* row = sgu_proj_w + (size_t)i * SDIM * SDIM + (size_t)s * SDIM;
        float acc = 0.0f;
        for (int t = threadIdx.x * 4; t < SDIM; t += blockDim.x * 4) {
            float4 v = *(const float4*)(row + t);
            acc += (v.x + v.y) + (v.z + v.w);
        }
        float rowsum = block_reduce_sum(acc, sbuf);
        if (threadIdx.x == 0) {
            float tln = ln1_b[i];  // LN over size-1 axis == bias
            float Gu  = gelu_exact(tln * cp1_w[i * 2 + 0] + cp1_b[i * 2 + 0]);
            float vp  = sgu_ln_b[i] * rowsum + sgu_proj_b[(size_t)i * SDIM + s];
            total += (Gu * vp) * cp2_w[i] + cp2_b[i];
        }
        __syncthreads();
    }
    if (threadIdx.x == 0) g_c[s] = total;
}

__global__ void compute_d_kernel(const float* __restrict__ pooler_w,
                                 const float* __restrict__ pooler_b) {
    __shared__ float sbuf[8];
    int sp = blockIdx.x;
    const float* row = pooler_w + (size_t)sp * SDIM;
    float acc = 0.0f;
    for (int t = threadIdx.x * 4; t < SDIM; t += blockDim.x * 4) {
        float4 v = *(const float4*)(row + t);
        acc += v.x * g_c[t] + v.y * g_c[t + 1] + v.z * g_c[t + 2] + v.w * g_c[t + 3];
    }
    float v = block_reduce_sum(acc, sbuf);
    if (threadIdx.x == 0) g_d[sp] = v + pooler_b[sp];
}

// ---------------- fp16 1-split GEMM (2 MMAs/K16), cp.async 4-stage, occ 2 ----------------
// stage layout: Ah @0, Al @8192, Bq @16384  (each 128 rows x 64B, swizzled)
__global__ void __launch_bounds__(256, 2)
gemm_hmma_kernel(const float* __restrict__ clsw) {
    extern __shared__ __align__(1024) char smem[];
    const uint32_t sb = smem_u32(smem);

    const int tid  = threadIdx.x;
    const int lane = tid & 31;
    const int wid  = tid >> 5;
    const int g    = lane >> 2;
    const int t4   = lane & 3;
    const int wm   = (wid & 3) * 32;
    const int wn   = (wid >> 2) * 64;
    const int bB   = blockIdx.y * BM;
    const int bS   = blockIdx.x * BN;

    // producer: thread -> row = tid/2, byte-col (tid&1)*32 (two 16B atoms per region)
    const int prow = tid >> 1;
    const int pcb  = (tid & 1) * 32;
    const char* XB = (const char*)g_xs + (size_t)(bB + prow) * 16384 + pcb;  // hi (lo at +8192)
    const char* WB = (const char*)g_wq + (size_t)(bS + prow) * 8192 + pcb;
    const uint32_t d0 = swz((uint32_t)(prow * 64 + pcb));
    const uint32_t d1 = swz((uint32_t)(prow * 64 + pcb + 16));

    // ldmatrix fragment offsets: kb*32 folded PRE-swizzle
    uint32_t offAm[2][2], offBn[4][2];
    {
        int r = lane & 15, kc = lane >> 4;
        #pragma unroll
        for (int mt = 0; mt < 2; ++mt)
            #pragma unroll
            for (int kb = 0; kb < 2; ++kb)
                offAm[mt][kb] = swz((uint32_t)((wm + mt * 16 + r) * 64 + kc * 16 + kb * 32));
        int rb = (lane & 7) + ((lane >> 4) << 3), kcb = (lane >> 3) & 1;
        #pragma unroll
        for (int np = 0; np < 4; ++np)
            #pragma unroll
            for (int kb = 0; kb < 2; ++kb)
                offBn[np][kb] = swz((uint32_t)((wn + np * 16 + rb) * 64 + kcb * 16 + kb * 32));
    }

    float acc[2][8][4];
    #pragma unroll
    for (int mt = 0; mt < 2; ++mt)
        #pragma unroll
        for (int nt = 0; nt < 8; ++nt)
            #pragma unroll
            for (int c = 0; c < 4; ++c) acc[mt][nt][c] = 0.0f;

    // issue one stage's loads: 6 x 16B per thread
    auto issue = [&](int stage, int ch) {
        const uint32_t stb = sb + stage * STGB;
        const int ko = ch * 64;            // BK halfs = 64 bytes
        CP_ASYNC_16(stb + d0,         XB + ko);
        CP_ASYNC_16(stb + d1,         XB + ko + 16);
        CP_ASYNC_16(stb + 8192 + d0,  XB + 8192 + ko);
        CP_ASYNC_16(stb + 8192 + d1,  XB + 8192 + ko + 16);
        CP_ASYNC_16(stb + 16384 + d0, WB + ko);
        CP_ASYNC_16(stb + 16384 + d1, WB + ko + 16);
    };

    #pragma unroll
    for (int s = 0; s < NSTAGE - 1; ++s) { issue(s, s); CP_COMMIT(); }

    int rd = 0, wr = NSTAGE - 1;
    #pragma unroll 1
    for (int ch = 0; ch < NCH; ++ch) {
        CP_WAIT(NSTAGE - 2);
        __syncthreads();

        if (ch + NSTAGE - 1 < NCH) issue(wr, ch + NSTAGE - 1);
        CP_COMMIT();
        if (++wr == NSTAGE) wr = 0;

        const uint32_t stb = sb + rd * STGB;
        if (++rd == NSTAGE) rd = 0;
        #pragma unroll
        for (int kb = 0; kb < 2; ++kb) {
            uint32_t aH[2][4], aL[2][4];
            #pragma unroll
            for (int mt = 0; mt < 2; ++mt) {
                LDSM_X4(aH[mt][0], aH[mt][1], aH[mt][2], aH[mt][3], stb + offAm[mt][kb]);
                LDSM_X4(aL[mt][0], aL[mt][1], aL[mt][2], aL[mt][3], stb + 8192 + offAm[mt][kb]);
            }
            #pragma unroll
            for (int np = 0; np < 4; ++np) {
                uint32_t bQ[4];
                LDSM_X4(bQ[0], bQ[1], bQ[2], bQ[3], stb + 16384 + offBn[np][kb]);
                #pragma unroll
                for (int mt = 0; mt < 2; ++mt) {
                    #pragma unroll
                    for (int j = 0; j < 2; ++j) {
                        float* c = acc[mt][np * 2 + j];
                        mma16816(c, aH[mt][0], aH[mt][1], aH[mt][2], aH[mt][3], bQ[2*j], bQ[2*j+1]);
                        mma16816(c, aL[mt][0], aL[mt][1], aL[mt][2], aL[mt][3], bQ[2*j], bQ[2*j+1]);
                    }
                }
            }
        }
    }

    // ---------------- fused epilogue ----------------
    CP_WAIT(0);
    float rs[4] = {0.0f, 0.0f, 0.0f, 0.0f};
    #pragma unroll
    for (int nt = 0; nt < 8; ++nt) {
        int col0 = bS + wn + nt * 8 + 2 * t4;
        float dd0 = g_d[col0],     w0 = clsw[col0];
        float dd1 = g_d[col0 + 1], w1 = clsw[col0 + 1];
        #pragma unroll
        for (int mt = 0; mt < 2; ++mt) {
            rs[mt * 2 + 0] += gelu_exact(acc[mt][nt][0] + dd0) * w0
                            + gelu_exact(acc[mt][nt][1] + dd1) * w1;
            rs[mt * 2 + 1] += gelu_exact(acc[mt][nt][2] + dd0) * w0
                            + gelu_exact(acc[mt][nt][3] + dd1) * w1;
        }
    }
    #pragma unroll
    for (int o = 1; o <= 2; o <<= 1) {
        #pragma unroll
        for (int i = 0; i < 4; ++i) rs[i] += __shfl_xor_sync(0xffffffffu, rs[i], o);
    }

    float* redbuf = (float*)smem;   // [2][128]
    __syncthreads();
    if (t4 == 0) {
        #pragma unroll
        for (int mt = 0; mt < 2; ++mt)
            #pragma unroll
            for (int h = 0; h < 2; ++h) {
                int row = wm + mt * 16 + h * 8 + g;
                redbuf[(wid >> 2) * 128 + row] = rs[mt * 2 + h];
            }
    }
    __syncthreads();
    if (tid < 128) {
        float p = redbuf[tid] + redbuf[128 + tid];
        g_partial[(size_t)(bB + tid) * NTILE + blockIdx.x] = p;
    }
}

__global__ void final_kernel(const float* __restrict__ cls_b, float* __restrict__ out) {
    int b = blockIdx.x * blockDim.x + threadIdx.x;
    if (b < BDIM) {
        float sum = 0.0f;
        #pragma unroll
        for (int j = 0; j < NTILE; ++j) sum += g_partial[(size_t)b * NTILE + j];
        out[b] = sum + cls_b[0];
    }
}

// ---------------- launch ----------------
extern "C" void kernel_launch(void* const* d_in, const int* in_sizes, int n_in,
                              void* d_out, int out_size) {
    const float* x          = (const float*)d_in[0];
    const float* ln1_b      = (const float*)d_in[2];
    const float* cp1_w      = (const float*)d_in[3];
    const float* cp1_b      = (const float*)d_in[4];
    const float* sgu_ln_b   = (const float*)d_in[6];
    const float* sgu_proj_w = (const float*)d_in[7];
    const float* sgu_proj_b = (const float*)d_in[8];
    const float* cp2_w      = (const float*)d_in[9];
    const float* cp2_b      = (const float*)d_in[10];
    const float* pooler_w   = (const float*)d_in[11];
    const float* pooler_b   = (const float*)d_in[12];
    const float* cls_w      = (const float*)d_in[13];
    const float* cls_b      = (const float*)d_in[14];

    cudaFuncSetAttribute(gemm_hmma_kernel, cudaFuncAttributeMaxDynamicSharedMemorySize,
                         NSTAGE * STGB);

    __half *xs, *wq;
    cudaGetSymbolAddress((void**)&xs, g_xs);
    cudaGetSymbolAddress((void**)&wq, g_wq);

    convert_x_kernel<<<(size_t)BDIM * SDIM / 1024, 256>>>(x, xs);
    convert_w_kernel<<<(size_t)SDIM * SDIM / 1024, 256>>>(pooler_w, wq);

    compute_c_kernel<<<SDIM, 256>>>(sgu_proj_w, sgu_proj_b, ln1_b, cp1_w, cp1_b,
                                    sgu_ln_b, cp2_w, cp2_b);
    compute_d_kernel<<<SDIM, 256>>>(pooler_w, pooler_b);

    dim3 grid(SDIM / BN, BDIM / BM);   // (32, 32)
    gemm_hmma_kernel<<<grid, 256, NSTAGE * STGB>>>(cls_w);

    final_kernel<<<(BDIM + 255) / 256, 256>>>(cls_b, (float*)d_out);
}

// round 16
// speedup vs baseline: 5.7641x; 1.5732x over previous
#include <cuda_runtime.h>
#include <cuda_fp16.h>
#include <math.h>
#include <stdint.h>

#define SDIM 4096
#define BDIM 4096
#define BM 128
#define BN 128
#define BK 32
#define NCH (SDIM / BK)      // 128
#define NTILE (SDIM / BN)    // 32
#define NSTAGE 4
#define STGB 16384           // per stage: Aq 8K, Bq 8K

// ---------------- scratch ----------------
__device__ float g_c[SDIM];
__device__ float g_d[SDIM];
__device__ float g_partial[(size_t)BDIM * NTILE];
__device__ __half g_xq[(size_t)BDIM * 4096];
__device__ __half g_wq[(size_t)SDIM * 4096];

// ---------------- helpers ----------------
__device__ __forceinline__ float gelu_exact(float x) {
    return 0.5f * x * (1.0f + erff(x * 0.70710678118654752f));
}

__device__ __forceinline__ uint32_t smem_u32(const void* p) {
    uint32_t a;
    asm("{ .reg .u64 t; cvta.to.shared.u64 t, %1; cvt.u32.u64 %0, t; }" : "=r"(a) : "l"(p));
    return a;
}

// swizzle for 64B rows: XOR byte bits [5:4] with row bits (off bits [8:7])
__device__ __forceinline__ uint32_t swz(uint32_t off) {
    return off ^ ((off >> 3) & 0x30);
}

#define CP_ASYNC_16(dst, src) \
    asm volatile("cp.async.cg.shared.global [%0], [%1], 16;" :: "r"(dst), "l"(src))
#define CP_COMMIT() asm volatile("cp.async.commit_group;" ::: "memory")
#define CP_WAIT(n)  asm volatile("cp.async.wait_group %0;" :: "n"(n) : "memory")

#define LDSM_X4(r0, r1, r2, r3, addr) \
    asm volatile("ldmatrix.sync.aligned.m8n8.x4.shared.b16 {%0,%1,%2,%3}, [%4];" \
        : "=r"(r0), "=r"(r1), "=r"(r2), "=r"(r3) : "r"(addr))

__device__ __forceinline__ void mma16816(float* c, uint32_t a0, uint32_t a1, uint32_t a2, uint32_t a3,
                                         uint32_t b0, uint32_t b1) {
    asm volatile("mma.sync.aligned.m16n8k16.row.col.f32.f16.f16.f32 "
        "{%0,%1,%2,%3}, {%4,%5,%6,%7}, {%8,%9}, {%0,%1,%2,%3};"
        : "+f"(c[0]), "+f"(c[1]), "+f"(c[2]), "+f"(c[3])
        : "r"(a0), "r"(a1), "r"(a2), "r"(a3), "r"(b0), "r"(b1));
}

__device__ __forceinline__ uint32_t pack_h2(__half a, __half b) {
    return (uint32_t)__half_as_ushort(a) | ((uint32_t)__half_as_ushort(b) << 16);
}

// ---------------- conversion: fp32 -> plain fp16 ----------------
__global__ void convert_h_kernel(const float* __restrict__ src, __half* __restrict__ dst) {
    size_t i = ((size_t)blockIdx.x * blockDim.x + threadIdx.x) * 4;
    float4 v = *(const float4*)(src + i);
    *(uint2*)(dst + i) = make_uint2(pack_h2(__float2half_rn(v.x), __float2half_rn(v.y)),
                                    pack_h2(__float2half_rn(v.z), __float2half_rn(v.w)));
}

// ---------------- prologue kernels ----------------
__device__ __forceinline__ float block_reduce_sum(float v, float* sbuf) {
    int lane = threadIdx.x & 31, warp = threadIdx.x >> 5;
    #pragma unroll
    for (int o = 16; o > 0; o >>= 1) v += __shfl_down_sync(0xffffffffu, v, o);
    if (lane == 0) sbuf[warp] = v;
    __syncthreads();
    if (warp == 0) {
        v = (lane < ((int)blockDim.x >> 5)) ? sbuf[lane] : 0.0f;
        #pragma unroll
        for (int o = 16; o > 0; o >>= 1) v += __shfl_down_sync(0xffffffffu, v, o);
    }
    return v;
}

__global__ void compute_c_kernel(const float* __restrict__ sgu_proj_w,
                                 const float* __restrict__ sgu_proj_b,
                                 const float* __restrict__ ln1_b,
                                 const float* __restrict__ cp1_w,
                                 const float* __restrict__ cp1_b,
                                 const float* __restrict__ sgu_ln_b,
                                 const float* __restrict__ cp2_w,
                                 const float* __restrict__ cp2_b) {
    __shared__ float sbuf[8];
    int s = blockIdx.x;
    float total = 0.0f;
    #pragma unroll
    for (int i = 0; i < 2; ++i) {
        const float* row = sgu_proj_w + (size_t)i * SDIM * SDIM + (size_t)s * SDIM;
        float acc = 0.0f;
        for (int t = threadIdx.x * 4; t < SDIM; t += blockDim.x * 4) {
            float4 v = *(const float4*)(row + t);
            acc += (v.x + v.y) + (v.z + v.w);
        }
        float rowsum = block_reduce_sum(acc, sbuf);
        if (threadIdx.x == 0) {
            float tln = ln1_b[i];  // LN over size-1 axis == bias
            float Gu  = gelu_exact(tln * cp1_w[i * 2 + 0] + cp1_b[i * 2 + 0]);
            float vp  = sgu_ln_b[i] * rowsum + sgu_proj_b[(size_t)i * SDIM + s];
            total += (Gu * vp) * cp2_w[i] + cp2_b[i];
        }
        __syncthreads();
    }
    if (threadIdx.x == 0) g_c[s] = total;
}

__global__ void compute_d_kernel(const float* __restrict__ pooler_w,
                                 const float* __restrict__ pooler_b) {
    __shared__ float sbuf[8];
    int sp = blockIdx.x;
    const float* row = pooler_w + (size_t)sp * SDIM;
    float acc = 0.0f;
    for (int t = threadIdx.x * 4; t < SDIM; t += blockDim.x * 4) {
        float4 v = *(const float4*)(row + t);
        acc += v.x * g_c[t] + v.y * g_c[t + 1] + v.z * g_c[t + 2] + v.w * g_c[t + 3];
    }
    float v = block_reduce_sum(acc, sbuf);
    if (threadIdx.x == 0) g_d[sp] = v + pooler_b[sp];
}

// ---------------- fp16 plain GEMM (1 MMA/K16), cp.async 4-stage, occ 2 ----------------
// stage layout: Aq @0, Bq @8192  (each 128 rows x 64B, swizzled)
__global__ void __launch_bounds__(256, 2)
gemm_hmma_kernel(const float* __restrict__ clsw) {
    extern __shared__ __align__(1024) char smem[];
    const uint32_t sb = smem_u32(smem);

    const int tid  = threadIdx.x;
    const int lane = tid & 31;
    const int wid  = tid >> 5;
    const int g    = lane >> 2;
    const int t4   = lane & 3;
    const int wm   = (wid & 3) * 32;
    const int wn   = (wid >> 2) * 64;
    const int bB   = blockIdx.y * BM;
    const int bS   = blockIdx.x * BN;

    // producer: thread -> row = tid/2, byte-col (tid&1)*32 (two 16B atoms per region)
    const int prow = tid >> 1;
    const int pcb  = (tid & 1) * 32;
    const char* XB = (const char*)g_xq + (size_t)(bB + prow) * 8192 + pcb;
    const char* WB = (const char*)g_wq + (size_t)(bS + prow) * 8192 + pcb;
    const uint32_t d0 = swz((uint32_t)(prow * 64 + pcb));
    const uint32_t d1 = swz((uint32_t)(prow * 64 + pcb + 16));

    // ldmatrix fragment offsets: kb*32 folded PRE-swizzle
    uint32_t offAm[2][2], offBn[4][2];
    {
        int r = lane & 15, kc = lane >> 4;
        #pragma unroll
        for (int mt = 0; mt < 2; ++mt)
            #pragma unroll
            for (int kb = 0; kb < 2; ++kb)
                offAm[mt][kb] = swz((uint32_t)((wm + mt * 16 + r) * 64 + kc * 16 + kb * 32));
        int rb = (lane & 7) + ((lane >> 4) << 3), kcb = (lane >> 3) & 1;
        #pragma unroll
        for (int np = 0; np < 4; ++np)
            #pragma unroll
            for (int kb = 0; kb < 2; ++kb)
                offBn[np][kb] = swz((uint32_t)((wn + np * 16 + rb) * 64 + kcb * 16 + kb * 32));
    }

    float acc[2][8][4];
    #pragma unroll
    for (int mt = 0; mt < 2; ++mt)
        #pragma unroll
        for (int nt = 0; nt < 8; ++nt)
            #pragma unroll
            for (int c = 0; c < 4; ++c) acc[mt][nt][c] = 0.0f;

    // issue one stage's loads: 4 x 16B per thread
    auto issue = [&](int stage, int ch) {
        const uint32_t stb = sb + stage * STGB;
        const int ko = ch * 64;            // BK halfs = 64 bytes
        CP_ASYNC_16(stb + d0,        XB + ko);
        CP_ASYNC_16(stb + d1,        XB + ko + 16);
        CP_ASYNC_16(stb + 8192 + d0, WB + ko);
        CP_ASYNC_16(stb + 8192 + d1, WB + ko + 16);
    };

    #pragma unroll
    for (int s = 0; s < NSTAGE - 1; ++s) { issue(s, s); CP_COMMIT(); }

    int rd = 0, wr = NSTAGE - 1;
    #pragma unroll 1
    for (int ch = 0; ch < NCH; ++ch) {
        CP_WAIT(NSTAGE - 2);
        __syncthreads();

        if (ch + NSTAGE - 1 < NCH) issue(wr, ch + NSTAGE - 1);
        CP_COMMIT();
        if (++wr == NSTAGE) wr = 0;

        const uint32_t stb = sb + rd * STGB;
        if (++rd == NSTAGE) rd = 0;
        #pragma unroll
        for (int kb = 0; kb < 2; ++kb) {
            uint32_t aQ[2][4];
            #pragma unroll
            for (int mt = 0; mt < 2; ++mt)
                LDSM_X4(aQ[mt][0], aQ[mt][1], aQ[mt][2], aQ[mt][3], stb + offAm[mt][kb]);
            #pragma unroll
            for (int np = 0; np < 4; ++np) {
                uint32_t bQ[4];
                LDSM_X4(bQ[0], bQ[1], bQ[2], bQ[3], stb + 8192 + offBn[np][kb]);
                #pragma unroll
                for (int mt = 0; mt < 2; ++mt) {
                    #pragma unroll
                    for (int j = 0; j < 2; ++j) {
                        float* c = acc[mt][np * 2 + j];
                        mma16816(c, aQ[mt][0], aQ[mt][1], aQ[mt][2], aQ[mt][3], bQ[2*j], bQ[2*j+1]);
                    }
                }
            }
        }
    }

    // ---------------- fused epilogue ----------------
    CP_WAIT(0);
    float rs[4] = {0.0f, 0.0f, 0.0f, 0.0f};
    #pragma unroll
    for (int nt = 0; nt < 8; ++nt) {
        int col0 = bS + wn + nt * 8 + 2 * t4;
        float dd0 = g_d[col0],     w0 = clsw[col0];
        float dd1 = g_d[col0 + 1], w1 = clsw[col0 + 1];
        #pragma unroll
        for (int mt = 0; mt < 2; ++mt) {
            rs[mt * 2 + 0] += gelu_exact(acc[mt][nt][0] + dd0) * w0
                            + gelu_exact(acc[mt][nt][1] + dd1) * w1;
            rs[mt * 2 + 1] += gelu_exact(acc[mt][nt][2] + dd0) * w0
                            + gelu_exact(acc[mt][nt][3] + dd1) * w1;
        }
    }
    #pragma unroll
    for (int o = 1; o <= 2; o <<= 1) {
        #pragma unroll
        for (int i = 0; i < 4; ++i) rs[i] += __shfl_xor_sync(0xffffffffu, rs[i], o);
    }

    float* redbuf = (float*)smem;   // [2][128]
    __syncthreads();
    if (t4 == 0) {
        #pragma unroll
        for (int mt = 0; mt < 2; ++mt)
            #pragma unroll
            for (int h = 0; h < 2; ++h) {
                int row = wm + mt * 16 + h * 8 + g;
                redbuf[(wid >> 2) * 128 + row] = rs[mt * 2 + h];
            }
    }
    __syncthreads();
    if (tid < 128) {
        float p = redbuf[tid] + redbuf[128 + tid];
        g_partial[(size_t)(bB + tid) * NTILE + blockIdx.x] = p;
    }
}

__global__ void final_kernel(const float* __restrict__ cls_b, float* __restrict__ out) {
    int b = blockIdx.x * blockDim.x + threadIdx.x;
    if (b < BDIM) {
        float sum = 0.0f;
        #pragma unroll
        for (int j = 0; j < NTILE; ++j) sum += g_partial[(size_t)b * NTILE + j];
        out[b] = sum + cls_b[0];
    }
}

// ---------------- launch ----------------
extern "C" void kernel_launch(void* const* d_in, const int* in_sizes, int n_in,
                              void* d_out, int out_size) {
    const float* x          = (const float*)d_in[0];
    const float* ln1_b      = (const float*)d_in[2];
    const float* cp1_w      = (const float*)d_in[3];
    const float* cp1_b      = (const float*)d_in[4];
    const float* sgu_ln_b   = (const float*)d_in[6];
    const float* sgu_proj_w = (const float*)d_in[7];
    const float* sgu_proj_b = (const float*)d_in[8];
    const float* cp2_w      = (const float*)d_in[9];
    const float* cp2_b      = (const float*)d_in[10];
    const float* pooler_w   = (const float*)d_in[11];
    const float* pooler_b   = (const float*)d_in[12];
    const float* cls_w      = (const float*)d_in[13];
    const float* cls_b      = (const float*)d_in[14];

    cudaFuncSetAttribute(gemm_hmma_kernel, cudaFuncAttributeMaxDynamicSharedMemorySize,
                         NSTAGE * STGB);

    __half *xq, *wq;
    cudaGetSymbolAddress((void**)&xq, g_xq);
    cudaGetSymbolAddress((void**)&wq, g_wq);

    convert_h_kernel<<<(size_t)BDIM * SDIM / 1024, 256>>>(x, xq);
    convert_h_kernel<<<(size_t)SDIM * SDIM / 1024, 256>>>(pooler_w, wq);

    compute_c_kernel<<<SDIM, 256>>>(sgu_proj_w, sgu_proj_b, ln1_b, cp1_w, cp1_b,
                                    sgu_ln_b, cp2_w, cp2_b);
    compute_d_kernel<<<SDIM, 256>>>(pooler_w, pooler_b);

    dim3 grid(SDIM / BN, BDIM / BM);   // (32, 32)
    gemm_hmma_kernel<<<grid, 256, NSTAGE * STGB>>>(cls_w);

    final_kernel<<<(BDIM + 255) / 256, 256>>>(cls_b, (float*)d_out);
}